// round 8
// baseline (speedup 1.0000x reference)
#include <cuda_runtime.h>
#include <cuda_bf16.h>
#include <cstdint>

// Sinkhorn, 32 x 1024 x 1024, tau=1, 10 iterations.
//   E = exp(s); even iter: a_i = 1/sum_j E_ij b_j ; odd iter: b_j = 1/sum_i E_ij a_i
//   out = exp(s) * a_i * b_j
// k1: streaming exp+pack (bf16 E) + rowsum -> a  (iter 0)
// k2: persistent; col pass (iter 1) + 4 FUSED passes (iters 2+3,4+5,6+7,8+9),
//     each fused pass reads the block's 128-row slab ONCE: computes a_i per row
//     (two warps share a row; acc[16]/lane) and accumulates column partials.
//     5 E reads + 5 barriers instead of 9 + 8.
// k3: streaming final out = exp(s)*a*b.

#define BATCH 32
#define N 1024
#define BPB 8                  // k2 blocks per batch; grid = 8 x 32 = 256
#define TPB 512

__device__ __nv_bfloat16 g_E[(size_t)BATCH * N * N];   // 64 MB
__device__ float g_part[2][BPB][BATCH][N];             // 2 MB double-buffered
__device__ float g_a[BATCH * N];
__device__ float g_b[BATCH * N];
__device__ unsigned g_bar[BATCH * 32];

__global__ void k_zero_bar() { g_bar[threadIdx.x * 32] = 0u; }

__device__ __forceinline__ float2 bf2f(uint32_t v) {
    return __bfloat1622float2(*reinterpret_cast<__nv_bfloat162*>(&v));
}

// ===========================================================================
// k1: E = exp(s) -> bf16, a_i = 1/rowsum.  grid (128, 32) x 256 thr.
__global__ void k1_exp_rowsum(const float* __restrict__ s) {
    const int w    = threadIdx.x >> 5;
    const int lane = threadIdx.x & 31;
    const int row  = blockIdx.x * 8 + w;
    const int b    = blockIdx.y;
    const size_t base = ((size_t)b * N + row) * N;

    float sum = 0.f;
    #pragma unroll
    for (int k = 0; k < 8; ++k) {
        const int j = (lane + 32 * k) * 4;
        float4 sv = *reinterpret_cast<const float4*>(s + base + j);
        float e0 = __expf(sv.x), e1 = __expf(sv.y);
        float e2 = __expf(sv.z), e3 = __expf(sv.w);
        __nv_bfloat162 p0 = __floats2bfloat162_rn(e0, e1);
        __nv_bfloat162 p1 = __floats2bfloat162_rn(e2, e3);
        uint2 packed;
        packed.x = *reinterpret_cast<uint32_t*>(&p0);
        packed.y = *reinterpret_cast<uint32_t*>(&p1);
        *reinterpret_cast<uint2*>(&g_E[base + j]) = packed;
        sum += (e0 + e1) + (e2 + e3);
    }
    #pragma unroll
    for (int o = 16; o > 0; o >>= 1) sum += __shfl_down_sync(0xFFFFFFFFu, sum, o);
    if (lane == 0) g_a[b * N + row] = 1.0f / sum;
}

// ===========================================================================
// k2: col pass (iter 1) + fused passes (iters 2..9) + final b combine.
__global__ void __launch_bounds__(TPB, 2) k2_gemv() {
    const int part = blockIdx.x;          // 0..7
    const int b    = blockIdx.y;          // 0..31
    const int w    = threadIdx.x >> 5;    // 0..15
    const int lane = threadIdx.x & 31;
    const size_t bN2 = (size_t)b * N * N;

    __shared__ float sh[N];               // b vector (4 KB)
    __shared__ float red[16][512];        // col-partials reduce (32 KB)
    __shared__ float rp[2][16];           // row-sum halves, double-buffered

    unsigned bar_target = 0;
    unsigned* const barp = &g_bar[b * 32];

    auto batch_barrier = [&]() {
        __threadfence();
        __syncthreads();
        bar_target += BPB;
        if (threadIdx.x == 0) {
            atomicAdd(barp, 1u);
            while (*(volatile unsigned*)barp < bar_target) { }
            __threadfence();
        }
        __syncthreads();
    };

    // ---------------- iter 1: column pass (block owns 128 cols) ----------------
    {
        for (int t = threadIdx.x; t < N / 4; t += TPB)
            reinterpret_cast<float4*>(sh)[t] =
                __ldcg(&reinterpret_cast<const float4*>(&g_a[b * N])[t]);
        __syncthreads();

        const int col = part * 128 + (lane & 15) * 8;
        const int rofs = w * 2 + (lane >> 4);
        const size_t cb = bN2 + col;
        float acc[8] = {0.f, 0.f, 0.f, 0.f, 0.f, 0.f, 0.f, 0.f};
        #pragma unroll 1
        for (int it4 = 0; it4 < 8; ++it4) {
            uint4 u[4];
            float av[4];
            #pragma unroll
            for (int v = 0; v < 4; ++v) {
                const int r = (it4 * 4 + v) * 32 + rofs;
                u[v]  = *reinterpret_cast<const uint4*>(&g_E[cb + (size_t)r * N]);
                av[v] = sh[r];
            }
            #pragma unroll
            for (int v = 0; v < 4; ++v) {
                float2 f0 = bf2f(u[v].x), f1 = bf2f(u[v].y);
                float2 f2 = bf2f(u[v].z), f3 = bf2f(u[v].w);
                acc[0] = fmaf(av[v], f0.x, acc[0]);
                acc[1] = fmaf(av[v], f0.y, acc[1]);
                acc[2] = fmaf(av[v], f1.x, acc[2]);
                acc[3] = fmaf(av[v], f1.y, acc[3]);
                acc[4] = fmaf(av[v], f2.x, acc[4]);
                acc[5] = fmaf(av[v], f2.y, acc[5]);
                acc[6] = fmaf(av[v], f3.x, acc[6]);
                acc[7] = fmaf(av[v], f3.y, acc[7]);
            }
        }
        #pragma unroll
        for (int k = 0; k < 8; ++k)
            acc[k] += __shfl_xor_sync(0xFFFFFFFFu, acc[k], 16);
        if (lane < 16) {
            #pragma unroll
            for (int k = 0; k < 8; ++k) red[w][(lane & 15) * 8 + k] = acc[k];
        }
        __syncthreads();
        if (threadIdx.x < 128) {
            float ssum = 0.f;
            #pragma unroll
            for (int ww = 0; ww < 16; ++ww) ssum += red[ww][threadIdx.x];
            g_b[b * N + part * 128 + threadIdx.x] = 1.0f / ssum;
        }
    }
    batch_barrier();

    // ---------------- fused passes p=1..4 (iters 2p, 2p+1) ----------------
    const int halfw   = w & 7;            // row-group index within iteration
    const int colofs  = (w >> 3) * 512 + lane * 8;

    #pragma unroll 1
    for (int p = 1; p <= 4; ++p) {
        // stage b into sh
        if (p == 1) {
            for (int t = threadIdx.x; t < N / 4; t += TPB)
                reinterpret_cast<float4*>(sh)[t] =
                    __ldcg(&reinterpret_cast<const float4*>(&g_b[b * N])[t]);
        } else {
            const int c = threadIdx.x * 2;
            float s0 = 0.f, s1 = 0.f;
            const int buf_prev = (p - 1) & 1;
            #pragma unroll
            for (int q = 0; q < BPB; ++q) {
                float2 pv = __ldcg(reinterpret_cast<const float2*>(
                    &g_part[buf_prev][q][b][c]));
                s0 += pv.x; s1 += pv.y;
            }
            sh[c]     = 1.0f / s0;
            sh[c + 1] = 1.0f / s1;
        }
        __syncthreads();

        float acc[16];
        #pragma unroll
        for (int k = 0; k < 16; ++k) acc[k] = 0.f;

        const bool store_a = (p == 4);

        #pragma unroll 1
        for (int t = 0; t < 16; ++t) {
            const int row = part * 128 + t * 8 + halfw;
            const size_t base = bN2 + (size_t)row * N + colofs;
            uint4 u0 = *reinterpret_cast<const uint4*>(&g_E[base]);
            uint4 u1 = *reinterpret_cast<const uint4*>(&g_E[base + 256]);

            // dot with b (row update)
            float4 b0 = *reinterpret_cast<const float4*>(&sh[colofs]);
            float4 b1 = *reinterpret_cast<const float4*>(&sh[colofs + 4]);
            float4 b2 = *reinterpret_cast<const float4*>(&sh[colofs + 256]);
            float4 b3 = *reinterpret_cast<const float4*>(&sh[colofs + 260]);
            float2 f0 = bf2f(u0.x), f1 = bf2f(u0.y), f2 = bf2f(u0.z), f3 = bf2f(u0.w);
            float2 g0 = bf2f(u1.x), g1 = bf2f(u1.y), g2 = bf2f(u1.z), g3 = bf2f(u1.w);
            float psum = 0.f;
            psum = fmaf(f0.x, b0.x, psum); psum = fmaf(f0.y, b0.y, psum);
            psum = fmaf(f1.x, b0.z, psum); psum = fmaf(f1.y, b0.w, psum);
            psum = fmaf(f2.x, b1.x, psum); psum = fmaf(f2.y, b1.y, psum);
            psum = fmaf(f3.x, b1.z, psum); psum = fmaf(f3.y, b1.w, psum);
            psum = fmaf(g0.x, b2.x, psum); psum = fmaf(g0.y, b2.y, psum);
            psum = fmaf(g1.x, b2.z, psum); psum = fmaf(g1.y, b2.w, psum);
            psum = fmaf(g2.x, b3.x, psum); psum = fmaf(g2.y, b3.y, psum);
            psum = fmaf(g3.x, b3.z, psum); psum = fmaf(g3.y, b3.w, psum);
            #pragma unroll
            for (int o = 16; o > 0; o >>= 1)
                psum += __shfl_xor_sync(0xFFFFFFFFu, psum, o);
            if (lane == 0) rp[t & 1][w] = psum;
            __syncthreads();
            const float ai = 1.0f / (rp[t & 1][halfw] + rp[t & 1][halfw + 8]);
            if (store_a && w < 8 && lane == 0) g_a[b * N + row] = ai;

            // column accumulation (col update partial)
            acc[0]  = fmaf(ai, f0.x, acc[0]);  acc[1]  = fmaf(ai, f0.y, acc[1]);
            acc[2]  = fmaf(ai, f1.x, acc[2]);  acc[3]  = fmaf(ai, f1.y, acc[3]);
            acc[4]  = fmaf(ai, f2.x, acc[4]);  acc[5]  = fmaf(ai, f2.y, acc[5]);
            acc[6]  = fmaf(ai, f3.x, acc[6]);  acc[7]  = fmaf(ai, f3.y, acc[7]);
            acc[8]  = fmaf(ai, g0.x, acc[8]);  acc[9]  = fmaf(ai, g0.y, acc[9]);
            acc[10] = fmaf(ai, g1.x, acc[10]); acc[11] = fmaf(ai, g1.y, acc[11]);
            acc[12] = fmaf(ai, g2.x, acc[12]); acc[13] = fmaf(ai, g2.y, acc[13]);
            acc[14] = fmaf(ai, g3.x, acc[14]); acc[15] = fmaf(ai, g3.y, acc[15]);
        }

        // block reduce: warp w's acc covers half (w>>3), cols lane*8(+256)
        *reinterpret_cast<float4*>(&red[w][lane * 8]) =
            make_float4(acc[0], acc[1], acc[2], acc[3]);
        *reinterpret_cast<float4*>(&red[w][lane * 8 + 4]) =
            make_float4(acc[4], acc[5], acc[6], acc[7]);
        *reinterpret_cast<float4*>(&red[w][256 + lane * 8]) =
            make_float4(acc[8], acc[9], acc[10], acc[11]);
        *reinterpret_cast<float4*>(&red[w][256 + lane * 8 + 4]) =
            make_float4(acc[12], acc[13], acc[14], acc[15]);
        __syncthreads();

        {
            const int c  = threadIdx.x * 2;          // global col pair
            const int hb = (c >> 9) * 8;             // warp group of this half
            const int ix = c & 511;
            float s0 = 0.f, s1 = 0.f;
            #pragma unroll
            for (int q = 0; q < 8; ++q) {
                s0 += red[hb + q][ix];
                s1 += red[hb + q][ix + 1];
            }
            *reinterpret_cast<float2*>(&g_part[p & 1][part][b][c]) =
                make_float2(s0, s1);
        }
        batch_barrier();
    }

    // ---------------- final: b_j from pass-4 partials (buf 0) ----------------
    if (threadIdx.x < 128) {
        const int c = part * 128 + threadIdx.x;
        float s0 = 0.f;
        #pragma unroll
        for (int q = 0; q < BPB; ++q)
            s0 += __ldcg(&g_part[0][q][b][c]);
        g_b[b * N + c] = 1.0f / s0;
    }
}

// ===========================================================================
// k3: out = exp(s) * a_i * b_j.  grid (128, 32) x 256 thr.
__global__ void k3_final(const float* __restrict__ s, float* __restrict__ out) {
    __shared__ float shb[N];
    const int w    = threadIdx.x >> 5;
    const int lane = threadIdx.x & 31;
    const int row  = blockIdx.x * 8 + w;
    const int b    = blockIdx.y;
    const size_t base = ((size_t)b * N + row) * N;

    for (int t = threadIdx.x; t < N / 4; t += 256)
        reinterpret_cast<float4*>(shb)[t] =
            reinterpret_cast<const float4*>(&g_b[b * N])[t];
    __syncthreads();

    const float a = g_a[b * N + row];
    #pragma unroll
    for (int k = 0; k < 8; ++k) {
        const int j = (lane + 32 * k) * 4;
        float4 sv = *reinterpret_cast<const float4*>(s + base + j);
        float4 o;
        o.x = __expf(sv.x) * (a * shb[j]);
        o.y = __expf(sv.y) * (a * shb[j + 1]);
        o.z = __expf(sv.z) * (a * shb[j + 2]);
        o.w = __expf(sv.w) * (a * shb[j + 3]);
        *reinterpret_cast<float4*>(out + base + j) = o;
    }
}

// ---------------------------------------------------------------------------
extern "C" void kernel_launch(void* const* d_in, const int* in_sizes, int n_in,
                              void* d_out, int out_size) {
    const float* s = (const float*)d_in[0];
    float* out = (float*)d_out;

    k_zero_bar<<<1, BATCH>>>();
    k1_exp_rowsum<<<dim3(128, BATCH), 256>>>(s);
    k2_gemv<<<dim3(BPB, BATCH), TPB>>>();
    k3_final<<<dim3(128, BATCH), 256>>>(s, out);
}

// round 9
// speedup vs baseline: 1.1833x; 1.1833x over previous
#include <cuda_runtime.h>
#include <cuda_fp16.h>
#include <cstdint>

// Sinkhorn, 32 x 1024 x 1024, tau=1, 10 iterations.
//   E = exp(s); even iter: a_i = 1/sum_j E_ij b_j ; odd iter: b_j = 1/sum_i E_ij a_i
//   out = exp(s) * a_i * b_j
// E stored once as fp16 (64 MB; 10 mantissa bits -> per-elem err < 5e-4).
// k1: streaming exp+pack + rowsum -> a (iter 0)
// k2: persistent GEMV iterations 1..9; 8 co-resident blocks per batch with a
//     per-batch atomic barrier; E (2 MB/batch) stays L2-resident.
// k3: streaming final out = float(E) * a * b  (reads E, NOT s: 192 MB not 256).

#define BATCH 32
#define N 1024
#define BPB 8                  // k2 blocks per batch; grid = 8 x 32 = 256
#define TPB 512
#define WPB 16

__device__ __half g_E[(size_t)BATCH * N * N];          // 64 MB
__device__ float g_a[BATCH * N];
__device__ float g_b[BATCH * N];
__device__ unsigned g_bar[BATCH * 32];

__global__ void k_zero_bar() { g_bar[threadIdx.x * 32] = 0u; }

__device__ __forceinline__ float2 h2f(uint32_t v) {
    return __half22float2(*reinterpret_cast<__half2*>(&v));
}

// ===========================================================================
// k1: E = exp(s) -> fp16, a_i = 1/rowsum.  grid (128, 32) x 256 thr.
__global__ void k1_exp_rowsum(const float* __restrict__ s) {
    const int w    = threadIdx.x >> 5;
    const int lane = threadIdx.x & 31;
    const int row  = blockIdx.x * 8 + w;
    const int b    = blockIdx.y;
    const size_t base = ((size_t)b * N + row) * N;

    float sum = 0.f;
    #pragma unroll
    for (int k = 0; k < 8; ++k) {
        const int j = (lane + 32 * k) * 4;
        float4 sv = *reinterpret_cast<const float4*>(s + base + j);
        float e0 = __expf(sv.x), e1 = __expf(sv.y);
        float e2 = __expf(sv.z), e3 = __expf(sv.w);
        __half2 p0 = __floats2half2_rn(e0, e1);
        __half2 p1 = __floats2half2_rn(e2, e3);
        uint2 packed;
        packed.x = *reinterpret_cast<uint32_t*>(&p0);
        packed.y = *reinterpret_cast<uint32_t*>(&p1);
        *reinterpret_cast<uint2*>(&g_E[base + j]) = packed;
        sum += (e0 + e1) + (e2 + e3);
    }
    #pragma unroll
    for (int o = 16; o > 0; o >>= 1) sum += __shfl_down_sync(0xFFFFFFFFu, sum, o);
    if (lane == 0) g_a[b * N + row] = 1.0f / sum;
}

// ===========================================================================
// k2: persistent GEMV iterations 1..9.
__global__ void __launch_bounds__(TPB, 2) k2_gemv() {
    const int part = blockIdx.x;          // 0..7
    const int b    = blockIdx.y;          // 0..31
    const int w    = threadIdx.x >> 5;    // 0..15
    const int lane = threadIdx.x & 31;
    const size_t bN2 = (size_t)b * N * N;

    __shared__ float sh[N];               // a or b staging (4 KB)
    __shared__ float red[WPB][128];       // col-pass reduction (8 KB)

    unsigned bar_target = 0;
    unsigned* const barp = &g_bar[b * 32];

    auto batch_barrier = [&]() {
        __threadfence();
        __syncthreads();
        bar_target += BPB;
        if (threadIdx.x == 0) {
            atomicAdd(barp, 1u);
            while (*(volatile unsigned*)barp < bar_target) { }
            __threadfence();
        }
        __syncthreads();
    };

    #pragma unroll 1
    for (int it = 1; it <= 9; ++it) {
        if (it & 1) {
            // ---- column pass: b_j = 1/sum_i E_ij a_i. Block owns 128 cols.
            for (int t = threadIdx.x; t < N / 4; t += TPB)
                reinterpret_cast<float4*>(sh)[t] =
                    __ldcg(&reinterpret_cast<const float4*>(&g_a[b * N])[t]);
            __syncthreads();

            const int col = part * 128 + (lane & 15) * 8;
            const int rofs = w * 2 + (lane >> 4);
            const size_t cb = bN2 + col;
            float acc[8] = {0.f, 0.f, 0.f, 0.f, 0.f, 0.f, 0.f, 0.f};
            #pragma unroll 1
            for (int it4 = 0; it4 < 8; ++it4) {
                uint4 u[4];
                float av[4];
                #pragma unroll
                for (int v = 0; v < 4; ++v) {
                    const int r = (it4 * 4 + v) * 32 + rofs;
                    u[v]  = *reinterpret_cast<const uint4*>(&g_E[cb + (size_t)r * N]);
                    av[v] = sh[r];
                }
                #pragma unroll
                for (int v = 0; v < 4; ++v) {
                    float2 f0 = h2f(u[v].x), f1 = h2f(u[v].y);
                    float2 f2 = h2f(u[v].z), f3 = h2f(u[v].w);
                    acc[0] = fmaf(av[v], f0.x, acc[0]);
                    acc[1] = fmaf(av[v], f0.y, acc[1]);
                    acc[2] = fmaf(av[v], f1.x, acc[2]);
                    acc[3] = fmaf(av[v], f1.y, acc[3]);
                    acc[4] = fmaf(av[v], f2.x, acc[4]);
                    acc[5] = fmaf(av[v], f2.y, acc[5]);
                    acc[6] = fmaf(av[v], f3.x, acc[6]);
                    acc[7] = fmaf(av[v], f3.y, acc[7]);
                }
            }
            #pragma unroll
            for (int k = 0; k < 8; ++k)
                acc[k] += __shfl_xor_sync(0xFFFFFFFFu, acc[k], 16);
            if (lane < 16) {
                #pragma unroll
                for (int k = 0; k < 8; ++k) red[w][(lane & 15) * 8 + k] = acc[k];
            }
            __syncthreads();
            if (threadIdx.x < 128) {
                float ssum = 0.f;
                #pragma unroll
                for (int ww = 0; ww < WPB; ++ww) ssum += red[ww][threadIdx.x];
                g_b[b * N + part * 128 + threadIdx.x] = 1.0f / ssum;
            }
        } else {
            // ---- row pass: a_i = 1/sum_j E_ij b_j. Warp per row, 8 rows/warp.
            for (int t = threadIdx.x; t < N / 4; t += TPB)
                reinterpret_cast<float4*>(sh)[t] =
                    __ldcg(&reinterpret_cast<const float4*>(&g_b[b * N])[t]);
            __syncthreads();

            #pragma unroll 1
            for (int rr = 0; rr < 8; ++rr) {
                const int row = part * 128 + rr * WPB + w;
                const size_t base = bN2 + (size_t)row * N;
                float sum = 0.f;
                #pragma unroll
                for (int k = 0; k < 4; ++k) {
                    const int j = lane * 8 + 256 * k;
                    uint4 u = *reinterpret_cast<const uint4*>(&g_E[base + j]);
                    float4 bv0 = *reinterpret_cast<const float4*>(sh + j);
                    float4 bv1 = *reinterpret_cast<const float4*>(sh + j + 4);
                    float2 f0 = h2f(u.x), f1 = h2f(u.y);
                    float2 f2 = h2f(u.z), f3 = h2f(u.w);
                    sum = fmaf(f0.x, bv0.x, sum); sum = fmaf(f0.y, bv0.y, sum);
                    sum = fmaf(f1.x, bv0.z, sum); sum = fmaf(f1.y, bv0.w, sum);
                    sum = fmaf(f2.x, bv1.x, sum); sum = fmaf(f2.y, bv1.y, sum);
                    sum = fmaf(f3.x, bv1.z, sum); sum = fmaf(f3.y, bv1.w, sum);
                }
                #pragma unroll
                for (int o = 16; o > 0; o >>= 1) sum += __shfl_down_sync(0xFFFFFFFFu, sum, o);
                if (lane == 0) g_a[b * N + row] = 1.0f / sum;
            }
        }
        if (it < 9) batch_barrier();
    }
}

// ===========================================================================
// k3: out = float(E) * a_i * b_j.  grid (128, 32) x 256 thr. Warp per row.
// Reads E (fp16, 64 MB) instead of s (fp32, 128 MB).
__global__ void k3_final(float* __restrict__ out) {
    __shared__ float shb[N];
    const int w    = threadIdx.x >> 5;
    const int lane = threadIdx.x & 31;
    const int row  = blockIdx.x * 8 + w;
    const int b    = blockIdx.y;
    const size_t base = ((size_t)b * N + row) * N;

    for (int t = threadIdx.x; t < N / 4; t += 256)
        reinterpret_cast<float4*>(shb)[t] =
            reinterpret_cast<const float4*>(&g_b[b * N])[t];
    __syncthreads();

    const float a = g_a[b * N + row];
    #pragma unroll
    for (int k = 0; k < 4; ++k) {
        const int j = lane * 8 + 256 * k;
        uint4 u = *reinterpret_cast<const uint4*>(&g_E[base + j]);
        float2 f0 = h2f(u.x), f1 = h2f(u.y);
        float2 f2 = h2f(u.z), f3 = h2f(u.w);
        float4 o0, o1;
        o0.x = f0.x * (a * shb[j + 0]);
        o0.y = f0.y * (a * shb[j + 1]);
        o0.z = f1.x * (a * shb[j + 2]);
        o0.w = f1.y * (a * shb[j + 3]);
        o1.x = f2.x * (a * shb[j + 4]);
        o1.y = f2.y * (a * shb[j + 5]);
        o1.z = f3.x * (a * shb[j + 6]);
        o1.w = f3.y * (a * shb[j + 7]);
        *reinterpret_cast<float4*>(out + base + j)     = o0;
        *reinterpret_cast<float4*>(out + base + j + 4) = o1;
    }
}

// ---------------------------------------------------------------------------
extern "C" void kernel_launch(void* const* d_in, const int* in_sizes, int n_in,
                              void* d_out, int out_size) {
    const float* s = (const float*)d_in[0];
    float* out = (float*)d_out;

    k_zero_bar<<<1, BATCH>>>();
    k1_exp_rowsum<<<dim3(128, BATCH), 256>>>(s);
    k2_gemv<<<dim3(BPB, BATCH), TPB>>>();
    k3_final<<<dim3(128, BATCH), 256>>>(out);
}

// round 10
// speedup vs baseline: 1.2264x; 1.0364x over previous
#include <cuda_runtime.h>
#include <cuda_fp16.h>
#include <cstdint>

// Sinkhorn, 32 x 1024 x 1024, tau=1, 10 iterations.
//   E = exp(s); even iter: a_i = 1/sum_j E_ij b_j ; odd iter: b_j = 1/sum_i E_ij a_i
//   out = float(E) * a_i * b_j
// E stored once as fp16 (64 MB). Three launches:
//   k1: streaming exp+pack + rowsum -> a (iter 0); block(0,0) zeroes barriers.
//   k2: persistent GEMV iterations 1..9; 8 co-resident blocks/batch, atomic
//       per-batch barrier; E (2 MB/batch) L2-resident.
//   k3: streaming final (reads E not s: 192 MB), R7-proven access pattern.

#define BATCH 32
#define N 1024
#define BPB 8                  // k2 blocks per batch; grid = 8 x 32 = 256
#define TPB 512
#define WPB 16

__device__ __half g_E[(size_t)BATCH * N * N];          // 64 MB
__device__ float g_a[BATCH * N];
__device__ float g_b[BATCH * N];
__device__ unsigned g_bar[BATCH * 32];

__device__ __forceinline__ float2 h2f(uint32_t v) {
    return __half22float2(*reinterpret_cast<__half2*>(&v));
}

// ===========================================================================
// k1: E = exp(s) -> fp16, a_i = 1/rowsum.  grid (128, 32) x 256 thr.
__global__ void k1_exp_rowsum(const float* __restrict__ s) {
    // zero the k2 barrier counters (k1 completes before k2 launches)
    if (blockIdx.x == 0 && blockIdx.y == 0 && threadIdx.x < BATCH)
        g_bar[threadIdx.x * 32] = 0u;

    const int w    = threadIdx.x >> 5;
    const int lane = threadIdx.x & 31;
    const int row  = blockIdx.x * 8 + w;
    const int b    = blockIdx.y;
    const size_t base = ((size_t)b * N + row) * N;

    float sum = 0.f;
    #pragma unroll
    for (int k = 0; k < 8; ++k) {
        const int j = (lane + 32 * k) * 4;
        float4 sv = *reinterpret_cast<const float4*>(s + base + j);
        float e0 = __expf(sv.x), e1 = __expf(sv.y);
        float e2 = __expf(sv.z), e3 = __expf(sv.w);
        __half2 p0 = __floats2half2_rn(e0, e1);
        __half2 p1 = __floats2half2_rn(e2, e3);
        uint2 packed;
        packed.x = *reinterpret_cast<uint32_t*>(&p0);
        packed.y = *reinterpret_cast<uint32_t*>(&p1);
        *reinterpret_cast<uint2*>(&g_E[base + j]) = packed;
        sum += (e0 + e1) + (e2 + e3);
    }
    #pragma unroll
    for (int o = 16; o > 0; o >>= 1) sum += __shfl_down_sync(0xFFFFFFFFu, sum, o);
    if (lane == 0) g_a[b * N + row] = 1.0f / sum;
}

// ===========================================================================
// k2: persistent GEMV iterations 1..9.
__global__ void __launch_bounds__(TPB, 2) k2_gemv() {
    const int part = blockIdx.x;          // 0..7
    const int b    = blockIdx.y;          // 0..31
    const int w    = threadIdx.x >> 5;    // 0..15
    const int lane = threadIdx.x & 31;
    const size_t bN2 = (size_t)b * N * N;

    __shared__ float sh[N];               // a or b staging (4 KB)
    __shared__ float red[WPB][128];       // col-pass reduction (8 KB)

    unsigned bar_target = 0;
    unsigned* const barp = &g_bar[b * 32];

    auto batch_barrier = [&]() {
        __threadfence();
        __syncthreads();
        bar_target += BPB;
        if (threadIdx.x == 0) {
            atomicAdd(barp, 1u);
            while (*(volatile unsigned*)barp < bar_target) { }
            __threadfence();
        }
        __syncthreads();
    };

    #pragma unroll 1
    for (int it = 1; it <= 9; ++it) {
        if (it & 1) {
            // ---- column pass: b_j = 1/sum_i E_ij a_i. Block owns 128 cols.
            for (int t = threadIdx.x; t < N / 4; t += TPB)
                reinterpret_cast<float4*>(sh)[t] =
                    __ldcg(&reinterpret_cast<const float4*>(&g_a[b * N])[t]);
            __syncthreads();

            const int col = part * 128 + (lane & 15) * 8;
            const int rofs = w * 2 + (lane >> 4);
            const size_t cb = bN2 + col;
            float acc[8] = {0.f, 0.f, 0.f, 0.f, 0.f, 0.f, 0.f, 0.f};
            #pragma unroll 1
            for (int it4 = 0; it4 < 8; ++it4) {
                uint4 u[4];
                float av[4];
                #pragma unroll
                for (int v = 0; v < 4; ++v) {
                    const int r = (it4 * 4 + v) * 32 + rofs;
                    u[v]  = *reinterpret_cast<const uint4*>(&g_E[cb + (size_t)r * N]);
                    av[v] = sh[r];
                }
                #pragma unroll
                for (int v = 0; v < 4; ++v) {
                    float2 f0 = h2f(u[v].x), f1 = h2f(u[v].y);
                    float2 f2 = h2f(u[v].z), f3 = h2f(u[v].w);
                    acc[0] = fmaf(av[v], f0.x, acc[0]);
                    acc[1] = fmaf(av[v], f0.y, acc[1]);
                    acc[2] = fmaf(av[v], f1.x, acc[2]);
                    acc[3] = fmaf(av[v], f1.y, acc[3]);
                    acc[4] = fmaf(av[v], f2.x, acc[4]);
                    acc[5] = fmaf(av[v], f2.y, acc[5]);
                    acc[6] = fmaf(av[v], f3.x, acc[6]);
                    acc[7] = fmaf(av[v], f3.y, acc[7]);
                }
            }
            #pragma unroll
            for (int k = 0; k < 8; ++k)
                acc[k] += __shfl_xor_sync(0xFFFFFFFFu, acc[k], 16);
            if (lane < 16) {
                #pragma unroll
                for (int k = 0; k < 8; ++k) red[w][(lane & 15) * 8 + k] = acc[k];
            }
            __syncthreads();
            if (threadIdx.x < 128) {
                float ssum = 0.f;
                #pragma unroll
                for (int ww = 0; ww < WPB; ++ww) ssum += red[ww][threadIdx.x];
                g_b[b * N + part * 128 + threadIdx.x] = 1.0f / ssum;
            }
        } else {
            // ---- row pass: a_i = 1/sum_j E_ij b_j. Warp per row, 8 rows/warp.
            for (int t = threadIdx.x; t < N / 4; t += TPB)
                reinterpret_cast<float4*>(sh)[t] =
                    __ldcg(&reinterpret_cast<const float4*>(&g_b[b * N])[t]);
            __syncthreads();

            #pragma unroll 1
            for (int rr = 0; rr < 8; ++rr) {
                const int row = part * 128 + rr * WPB + w;
                const size_t base = bN2 + (size_t)row * N;
                float sum = 0.f;
                #pragma unroll
                for (int k = 0; k < 4; ++k) {
                    const int j = lane * 8 + 256 * k;
                    uint4 u = *reinterpret_cast<const uint4*>(&g_E[base + j]);
                    float4 bv0 = *reinterpret_cast<const float4*>(sh + j);
                    float4 bv1 = *reinterpret_cast<const float4*>(sh + j + 4);
                    float2 f0 = h2f(u.x), f1 = h2f(u.y);
                    float2 f2 = h2f(u.z), f3 = h2f(u.w);
                    sum = fmaf(f0.x, bv0.x, sum); sum = fmaf(f0.y, bv0.y, sum);
                    sum = fmaf(f1.x, bv0.z, sum); sum = fmaf(f1.y, bv0.w, sum);
                    sum = fmaf(f2.x, bv1.x, sum); sum = fmaf(f2.y, bv1.y, sum);
                    sum = fmaf(f3.x, bv1.z, sum); sum = fmaf(f3.y, bv1.w, sum);
                }
                #pragma unroll
                for (int o = 16; o > 0; o >>= 1) sum += __shfl_down_sync(0xFFFFFFFFu, sum, o);
                if (lane == 0) g_a[b * N + row] = 1.0f / sum;
            }
        }
        if (it < 9) batch_barrier();
    }
}

// ===========================================================================
// k3: out = float(E) * a_i * b_j.  grid (128, 32) x 256 thr. Warp per row.
// R7-proven pattern: j=(lane+32k)*4 -> contiguous 16 B stores per lane,
// 8 independent 8 B E loads, conflict-free float4 shared reads.
__global__ void k3_final(float* __restrict__ out) {
    __shared__ float shb[N];
    const int w    = threadIdx.x >> 5;
    const int lane = threadIdx.x & 31;
    const int row  = blockIdx.x * 8 + w;
    const int b    = blockIdx.y;
    const size_t base = ((size_t)b * N + row) * N;

    for (int t = threadIdx.x; t < N / 4; t += 256)
        reinterpret_cast<float4*>(shb)[t] =
            reinterpret_cast<const float4*>(&g_b[b * N])[t];
    __syncthreads();

    const float a = g_a[b * N + row];
    #pragma unroll
    for (int k = 0; k < 8; ++k) {
        const int j = (lane + 32 * k) * 4;
        uint2 u = *reinterpret_cast<const uint2*>(&g_E[base + j]);
        float2 f0 = h2f(u.x), f1 = h2f(u.y);
        float4 bv = *reinterpret_cast<const float4*>(&shb[j]);
        float4 o;
        o.x = f0.x * (a * bv.x);
        o.y = f0.y * (a * bv.y);
        o.z = f1.x * (a * bv.z);
        o.w = f1.y * (a * bv.w);
        *reinterpret_cast<float4*>(out + base + j) = o;
    }
}

// ---------------------------------------------------------------------------
extern "C" void kernel_launch(void* const* d_in, const int* in_sizes, int n_in,
                              void* d_out, int out_size) {
    const float* s = (const float*)d_in[0];
    float* out = (float*)d_out;

    k1_exp_rowsum<<<dim3(128, BATCH), 256>>>(s);
    k2_gemv<<<dim3(BPB, BATCH), TPB>>>();
    k3_final<<<dim3(128, BATCH), 256>>>(out);
}

// round 11
// speedup vs baseline: 1.2531x; 1.0218x over previous
#include <cuda_runtime.h>
#include <cuda_fp16.h>
#include <cstdint>

// Sinkhorn, 32 x 1024 x 1024, tau=1, 10 iterations.
//   E = exp(s); even iter: a_i = 1/sum_j E_ij b_j ; odd iter: b_j = 1/sum_i E_ij a_i
//   out = float(E) * a_i * b_j
// E stored once as fp16 (64 MB). Three launches:
//   k1: streaming exp+pack + rowsum -> a (iter 0); block(0,0) zeroes barriers.
//   k2: persistent GEMV iterations 1..8 (4 col + 4 row), 8 co-resident
//       blocks/batch with per-batch atomic barrier; E L2-resident.
//   k3: column-sliced final — Phase A computes iter 9 (col pass) with a
//       block-LOCAL reduction (block owns 128 cols x all rows), Phase B
//       re-sweeps the L2-hot slab writing out = E * a * b.

#define BATCH 32
#define N 1024
#define BPB 8                  // blocks per batch; grid = 8 x 32 = 256
#define TPB 512
#define WPB 16

__device__ __half g_E[(size_t)BATCH * N * N];          // 64 MB
__device__ float g_a[BATCH * N];
__device__ float g_b[BATCH * N];
__device__ unsigned g_bar[BATCH * 32];

__device__ __forceinline__ float2 h2f(uint32_t v) {
    return __half22float2(*reinterpret_cast<__half2*>(&v));
}

// ===========================================================================
// k1: E = exp(s) -> fp16, a_i = 1/rowsum.  grid (128, 32) x 256 thr.
__global__ void k1_exp_rowsum(const float* __restrict__ s) {
    if (blockIdx.x == 0 && blockIdx.y == 0 && threadIdx.x < BATCH)
        g_bar[threadIdx.x * 32] = 0u;

    const int w    = threadIdx.x >> 5;
    const int lane = threadIdx.x & 31;
    const int row  = blockIdx.x * 8 + w;
    const int b    = blockIdx.y;
    const size_t base = ((size_t)b * N + row) * N;

    float sum = 0.f;
    #pragma unroll
    for (int k = 0; k < 8; ++k) {
        const int j = (lane + 32 * k) * 4;
        float4 sv = *reinterpret_cast<const float4*>(s + base + j);
        float e0 = __expf(sv.x), e1 = __expf(sv.y);
        float e2 = __expf(sv.z), e3 = __expf(sv.w);
        __half2 p0 = __floats2half2_rn(e0, e1);
        __half2 p1 = __floats2half2_rn(e2, e3);
        uint2 packed;
        packed.x = *reinterpret_cast<uint32_t*>(&p0);
        packed.y = *reinterpret_cast<uint32_t*>(&p1);
        *reinterpret_cast<uint2*>(&g_E[base + j]) = packed;
        sum += (e0 + e1) + (e2 + e3);
    }
    #pragma unroll
    for (int o = 16; o > 0; o >>= 1) sum += __shfl_down_sync(0xFFFFFFFFu, sum, o);
    if (lane == 0) g_a[b * N + row] = 1.0f / sum;
}

// ===========================================================================
// k2: persistent GEMV iterations 1..8 (ends on a row pass writing g_a).
__global__ void __launch_bounds__(TPB, 2) k2_gemv() {
    const int part = blockIdx.x;          // 0..7
    const int b    = blockIdx.y;          // 0..31
    const int w    = threadIdx.x >> 5;    // 0..15
    const int lane = threadIdx.x & 31;
    const size_t bN2 = (size_t)b * N * N;

    __shared__ float sh[N];               // a or b staging (4 KB)
    __shared__ float red[WPB][128];       // col-pass reduction (8 KB)

    unsigned bar_target = 0;
    unsigned* const barp = &g_bar[b * 32];

    auto batch_barrier = [&]() {
        __threadfence();
        __syncthreads();
        bar_target += BPB;
        if (threadIdx.x == 0) {
            atomicAdd(barp, 1u);
            while (*(volatile unsigned*)barp < bar_target) { }
            __threadfence();
        }
        __syncthreads();
    };

    #pragma unroll 1
    for (int it = 1; it <= 8; ++it) {
        if (it & 1) {
            // ---- column pass: b_j = 1/sum_i E_ij a_i. Block owns 128 cols.
            for (int t = threadIdx.x; t < N / 4; t += TPB)
                reinterpret_cast<float4*>(sh)[t] =
                    __ldcg(&reinterpret_cast<const float4*>(&g_a[b * N])[t]);
            __syncthreads();

            const int col = part * 128 + (lane & 15) * 8;
            const int rofs = w * 2 + (lane >> 4);
            const size_t cb = bN2 + col;
            float acc[8] = {0.f, 0.f, 0.f, 0.f, 0.f, 0.f, 0.f, 0.f};
            #pragma unroll 1
            for (int it4 = 0; it4 < 8; ++it4) {
                uint4 u[4];
                float av[4];
                #pragma unroll
                for (int v = 0; v < 4; ++v) {
                    const int r = (it4 * 4 + v) * 32 + rofs;
                    u[v]  = *reinterpret_cast<const uint4*>(&g_E[cb + (size_t)r * N]);
                    av[v] = sh[r];
                }
                #pragma unroll
                for (int v = 0; v < 4; ++v) {
                    float2 f0 = h2f(u[v].x), f1 = h2f(u[v].y);
                    float2 f2 = h2f(u[v].z), f3 = h2f(u[v].w);
                    acc[0] = fmaf(av[v], f0.x, acc[0]);
                    acc[1] = fmaf(av[v], f0.y, acc[1]);
                    acc[2] = fmaf(av[v], f1.x, acc[2]);
                    acc[3] = fmaf(av[v], f1.y, acc[3]);
                    acc[4] = fmaf(av[v], f2.x, acc[4]);
                    acc[5] = fmaf(av[v], f2.y, acc[5]);
                    acc[6] = fmaf(av[v], f3.x, acc[6]);
                    acc[7] = fmaf(av[v], f3.y, acc[7]);
                }
            }
            #pragma unroll
            for (int k = 0; k < 8; ++k)
                acc[k] += __shfl_xor_sync(0xFFFFFFFFu, acc[k], 16);
            if (lane < 16) {
                #pragma unroll
                for (int k = 0; k < 8; ++k) red[w][(lane & 15) * 8 + k] = acc[k];
            }
            __syncthreads();
            if (threadIdx.x < 128) {
                float ssum = 0.f;
                #pragma unroll
                for (int ww = 0; ww < WPB; ++ww) ssum += red[ww][threadIdx.x];
                g_b[b * N + part * 128 + threadIdx.x] = 1.0f / ssum;
            }
        } else {
            // ---- row pass: a_i = 1/sum_j E_ij b_j. Warp per row, 8 rows/warp.
            for (int t = threadIdx.x; t < N / 4; t += TPB)
                reinterpret_cast<float4*>(sh)[t] =
                    __ldcg(&reinterpret_cast<const float4*>(&g_b[b * N])[t]);
            __syncthreads();

            #pragma unroll 1
            for (int rr = 0; rr < 8; ++rr) {
                const int row = part * 128 + rr * WPB + w;
                const size_t base = bN2 + (size_t)row * N;
                float sum = 0.f;
                #pragma unroll
                for (int k = 0; k < 4; ++k) {
                    const int j = lane * 8 + 256 * k;
                    uint4 u = *reinterpret_cast<const uint4*>(&g_E[base + j]);
                    float4 bv0 = *reinterpret_cast<const float4*>(sh + j);
                    float4 bv1 = *reinterpret_cast<const float4*>(sh + j + 4);
                    float2 f0 = h2f(u.x), f1 = h2f(u.y);
                    float2 f2 = h2f(u.z), f3 = h2f(u.w);
                    sum = fmaf(f0.x, bv0.x, sum); sum = fmaf(f0.y, bv0.y, sum);
                    sum = fmaf(f1.x, bv0.z, sum); sum = fmaf(f1.y, bv0.w, sum);
                    sum = fmaf(f2.x, bv1.x, sum); sum = fmaf(f2.y, bv1.y, sum);
                    sum = fmaf(f3.x, bv1.z, sum); sum = fmaf(f3.y, bv1.w, sum);
                }
                #pragma unroll
                for (int o = 16; o > 0; o >>= 1) sum += __shfl_down_sync(0xFFFFFFFFu, sum, o);
                if (lane == 0) g_a[b * N + row] = 1.0f / sum;
            }
        }
        if (it < 8) batch_barrier();
    }
}

// ===========================================================================
// k3: iter 9 (col pass, block-local) + final output. grid (8, 32) x 512 thr.
// Block owns 128 cols x all 1024 rows of batch b.
__global__ void __launch_bounds__(TPB) k3_final(float* __restrict__ out) {
    __shared__ float sha[N];              // a (from iter 8)
    __shared__ float red[WPB][128];
    __shared__ float shb[128];            // this block's b slice
    const int part = blockIdx.x;
    const int b    = blockIdx.y;
    const int w    = threadIdx.x >> 5;
    const int lane = threadIdx.x & 31;
    const size_t bN2 = (size_t)b * N * N;

    for (int t = threadIdx.x; t < N / 4; t += TPB)
        reinterpret_cast<float4*>(sha)[t] =
            reinterpret_cast<const float4*>(&g_a[b * N])[t];
    __syncthreads();

    // ---- Phase A: iter 9 column sums (block-local; k2 col-pass pattern) ----
    {
        const int col = part * 128 + (lane & 15) * 8;
        const int rofs = w * 2 + (lane >> 4);
        const size_t cb = bN2 + col;
        float acc[8] = {0.f, 0.f, 0.f, 0.f, 0.f, 0.f, 0.f, 0.f};
        #pragma unroll 1
        for (int it4 = 0; it4 < 8; ++it4) {
            uint4 u[4];
            float av[4];
            #pragma unroll
            for (int v = 0; v < 4; ++v) {
                const int r = (it4 * 4 + v) * 32 + rofs;
                u[v]  = *reinterpret_cast<const uint4*>(&g_E[cb + (size_t)r * N]);
                av[v] = sha[r];
            }
            #pragma unroll
            for (int v = 0; v < 4; ++v) {
                float2 f0 = h2f(u[v].x), f1 = h2f(u[v].y);
                float2 f2 = h2f(u[v].z), f3 = h2f(u[v].w);
                acc[0] = fmaf(av[v], f0.x, acc[0]);
                acc[1] = fmaf(av[v], f0.y, acc[1]);
                acc[2] = fmaf(av[v], f1.x, acc[2]);
                acc[3] = fmaf(av[v], f1.y, acc[3]);
                acc[4] = fmaf(av[v], f2.x, acc[4]);
                acc[5] = fmaf(av[v], f2.y, acc[5]);
                acc[6] = fmaf(av[v], f3.x, acc[6]);
                acc[7] = fmaf(av[v], f3.y, acc[7]);
            }
        }
        #pragma unroll
        for (int k = 0; k < 8; ++k)
            acc[k] += __shfl_xor_sync(0xFFFFFFFFu, acc[k], 16);
        if (lane < 16) {
            #pragma unroll
            for (int k = 0; k < 8; ++k) red[w][(lane & 15) * 8 + k] = acc[k];
        }
        __syncthreads();
        if (threadIdx.x < 128) {
            float ssum = 0.f;
            #pragma unroll
            for (int ww = 0; ww < WPB; ++ww) ssum += red[ww][threadIdx.x];
            shb[threadIdx.x] = 1.0f / ssum;
        }
        __syncthreads();
    }

    // ---- Phase B: out_ij = E_ij * a_i * b_j (slab is L2-hot) ----
    // Warp w owns rows [w*64, w*64+64); lane covers 4 cols -> warp stores
    // 512 B contiguous per row.
    {
        const int c4 = lane * 4;
        const float4 bv = *reinterpret_cast<const float4*>(&shb[c4]);
        const size_t cbase = bN2 + part * 128 + c4;
        #pragma unroll 1
        for (int t = 0; t < 16; ++t) {
            const int r0 = w * 64 + t * 4;
            uint2  e[4];
            float  av[4];
            #pragma unroll
            for (int v = 0; v < 4; ++v) {
                e[v]  = *reinterpret_cast<const uint2*>(&g_E[cbase + (size_t)(r0 + v) * N]);
                av[v] = sha[r0 + v];
            }
            #pragma unroll
            for (int v = 0; v < 4; ++v) {
                float2 f0 = h2f(e[v].x), f1 = h2f(e[v].y);
                float4 o;
                o.x = f0.x * (av[v] * bv.x);
                o.y = f0.y * (av[v] * bv.y);
                o.z = f1.x * (av[v] * bv.z);
                o.w = f1.y * (av[v] * bv.w);
                *reinterpret_cast<float4*>(out + cbase + (size_t)(r0 + v) * N) = o;
            }
        }
    }
}

// ---------------------------------------------------------------------------
extern "C" void kernel_launch(void* const* d_in, const int* in_sizes, int n_in,
                              void* d_out, int out_size) {
    const float* s = (const float*)d_in[0];
    float* out = (float*)d_out;

    k1_exp_rowsum<<<dim3(128, BATCH), 256>>>(s);
    k2_gemv<<<dim3(BPB, BATCH), TPB>>>();
    k3_final<<<dim3(BPB, BATCH), TPB>>>(out);
}